// round 1
// baseline (speedup 1.0000x reference)
#include <cuda_runtime.h>
#include <math.h>
#include <stdint.h>

#define C_     32
#define NC_    2000
#define N_     10000
#define E_     30000
#define D_     128
#define L_     4
#define F_FEAT 140
#define F_CFG  18
#define F_EMB  4

// ---------------- scratch (static device globals; no allocation) ----------------
__device__ float g_x   [(size_t)C_ * N_ * D_];   // activations  (C,N,128)
__device__ float g_agg [(size_t)C_ * N_ * D_];   // propagated   (C,N,128)
__device__ float g_base[(size_t)N_ * D_];        // config-independent input projection
__device__ float g_bias2[D_];                    // b_lin - 2*sum(W_cfg rows)
__device__ float g_invdeg[N_];
__device__ int   g_cnt [N_];
__device__ int   g_fill[N_];
__device__ int   g_indptr[N_ + 1];
__device__ int   g_csr[E_];
__device__ float g_pool[C_ * D_];

// ---------------- graph preprocessing ----------------
__global__ void k_count(const int* __restrict__ dst, int E) {
    int e = blockIdx.x * blockDim.x + threadIdx.x;
    if (e < E) atomicAdd(&g_cnt[dst[e]], 1);
}

// single-block exclusive scan over g_cnt -> g_indptr, also writes inv_deg
__global__ void k_scan() {
    const int T = 1024, CH = 10;             // 1024*10 >= N_
    int t = threadIdx.x;
    int base = t * CH;
    int vals[CH];
    int s = 0;
#pragma unroll
    for (int i = 0; i < CH; i++) {
        int idx = base + i;
        int v = (idx < N_) ? g_cnt[idx] : 0;
        vals[i] = v; s += v;
    }
    int lane = t & 31, wid = t >> 5;
    int inc = s;
#pragma unroll
    for (int o = 1; o < 32; o <<= 1) {
        int y = __shfl_up_sync(0xffffffffu, inc, o);
        if (lane >= o) inc += y;
    }
    __shared__ int wtot[32];
    if (lane == 31) wtot[wid] = inc;
    __syncthreads();
    if (wid == 0) {
        int v = wtot[lane];
#pragma unroll
        for (int o = 1; o < 32; o <<= 1) {
            int y = __shfl_up_sync(0xffffffffu, v, o);
            if (lane >= o) v += y;
        }
        wtot[lane] = v;
    }
    __syncthreads();
    int excl = inc - s + (wid > 0 ? wtot[wid - 1] : 0);
    int run = excl;
#pragma unroll
    for (int i = 0; i < CH; i++) {
        int idx = base + i;
        if (idx < N_) {
            g_indptr[idx] = run;
            g_invdeg[idx] = 1.0f / fmaxf((float)vals[i], 1.0f);
        }
        run += vals[i];
    }
    if (t == T - 1) g_indptr[N_] = run;
}

__global__ void k_fill(const int* __restrict__ src, const int* __restrict__ dst, int E) {
    int e = blockIdx.x * blockDim.x + threadIdx.x;
    if (e < E) {
        int d = dst[e];
        int pos = g_indptr[d] + atomicAdd(&g_fill[d], 1);
        g_csr[pos] = src[e];
    }
}

// ---------------- input projection ----------------
// bias2[j] = b_lin[j] + (-2) * sum_k W_cfg[k][j]
__global__ void k_bias2(const float* __restrict__ W_lin, const float* __restrict__ b_lin) {
    int j = threadIdx.x;
    float s = b_lin[j];
#pragma unroll
    for (int k = 0; k < F_CFG; k++) s -= 2.0f * W_lin[(F_FEAT + k) * D_ + j];
    g_bias2[j] = s;
}

// base[n] = feat[n]@W_feat + emb[x_op[n]]@W_emb + bias2    (16 nodes / block)
__global__ void k_base(const float* __restrict__ x_feat, const int* __restrict__ x_op,
                       const float* __restrict__ emb, const float* __restrict__ W_lin) {
    __shared__ float s_in[16][F_FEAT + F_EMB];
    int n0 = blockIdx.x * 16;
    int tid = threadIdx.x;
    for (int i = tid; i < 16 * F_FEAT; i += 128) {
        int m = i / F_FEAT, k = i % F_FEAT;
        s_in[m][k] = x_feat[(size_t)(n0 + m) * F_FEAT + k];
    }
    if (tid < 16 * F_EMB) {
        int m = tid / F_EMB, k = tid % F_EMB;
        s_in[m][F_FEAT + k] = emb[x_op[n0 + m] * F_EMB + k];
    }
    __syncthreads();
    float acc[16];
    float b = g_bias2[tid];
#pragma unroll
    for (int m = 0; m < 16; m++) acc[m] = b;
    const float* Wc = W_lin + tid;
#pragma unroll 4
    for (int k = 0; k < F_FEAT; k++) {
        float w = Wc[k * D_];
#pragma unroll
        for (int m = 0; m < 16; m++) acc[m] += s_in[m][k] * w;
    }
#pragma unroll
    for (int k = 0; k < F_EMB; k++) {
        float w = Wc[(F_FEAT + F_CFG + k) * D_];
#pragma unroll
        for (int m = 0; m < 16; m++) acc[m] += s_in[m][F_FEAT + k] * w;
    }
#pragma unroll
    for (int m = 0; m < 16; m++) g_base[(size_t)(n0 + m) * D_ + tid] = acc[m];
}

__global__ void k_broadcast() {
    int c = blockIdx.y;
    int i = blockIdx.x * blockDim.x + threadIdx.x;          // float4 index in slice
    float4 v = ((const float4*)g_base)[i];
    ((float4*)g_x)[(size_t)c * (N_ * (D_ / 4)) + i] = v;
}

// per-config correction at config nodes: x[c,nid[j]] += (cfg[c,j]+2) @ W_cfg
// last-occurrence-wins for duplicate sorted ids
__global__ void k_correct(const float* __restrict__ xcfg, const int* __restrict__ nid,
                          const float* __restrict__ W_lin) {
    int j = blockIdx.x, c = blockIdx.y, tid = threadIdx.x;
    int n = nid[j];
    if (j < NC_ - 1 && nid[j + 1] == n) return;             // uniform per block
    __shared__ float s_cfg[F_CFG];
    if (tid < F_CFG) s_cfg[tid] = xcfg[((size_t)c * NC_ + j) * F_CFG + tid] + 2.0f;
    __syncthreads();
    float acc = 0.f;
#pragma unroll
    for (int k = 0; k < F_CFG; k++) acc += s_cfg[k] * W_lin[(F_FEAT + k) * D_ + tid];
    g_x[((size_t)c * N_ + n) * D_ + tid] += acc;
}

// ---------------- GNN propagation: agg[c,n] = inv_deg[n] * sum_{src in-edges} x[c,src]
__global__ void k_prop() {
    int gw = (blockIdx.x * blockDim.x + threadIdx.x) >> 5;
    int lane = threadIdx.x & 31;
    if (gw >= C_ * N_) return;
    int c = gw / N_, n = gw - c * N_;
    int beg = g_indptr[n], end = g_indptr[n + 1];
    const float* xb = g_x + (size_t)c * N_ * D_;
    float4 s = make_float4(0.f, 0.f, 0.f, 0.f);
    for (int e = beg; e < end; e++) {
        int src = g_csr[e];
        float4 v = *(const float4*)(xb + (size_t)src * D_ + lane * 4);
        s.x += v.x; s.y += v.y; s.z += v.z; s.w += v.w;
    }
    float id = g_invdeg[n];
    s.x *= id; s.y *= id; s.z *= id; s.w *= id;
    *(float4*)(g_agg + ((size_t)c * N_ + n) * D_ + lane * 4) = s;
}

// ---------------- fused dual GEMM: x = relu(agg@Wl + x@Wr + b), in-place on g_x
// 128x128 tile / block, 256 threads, 8x8 micro-tile, packed fma.rn.f32x2 (FFMA2)
__global__ void __launch_bounds__(256) k_gemm(const float* __restrict__ Wl,
                                              const float* __restrict__ Wr,
                                              const float* __restrict__ bias) {
    __shared__ __align__(16) float As[2][16][132];
    __shared__ __align__(16) float Bs[2][16][128];
    const int tid = threadIdx.x;
    const int tx = tid & 15, ty = tid >> 4;
    const size_t row0 = (size_t)blockIdx.x * 128;

    unsigned long long accp[4][8];
#pragma unroll
    for (int i = 0; i < 4; i++)
#pragma unroll
        for (int j = 0; j < 8; j++) accp[i][j] = 0ULL;

    auto loadStage = [&](int s, int buf) {
        int ks = s * 16;                                   // 0..255 combined K
        const float* asrc = (ks < 128) ? g_agg : g_x;
        const float* wsrc = (ks < 128) ? Wl : Wr;
        int kc = ks & 127;
#pragma unroll
        for (int q = 0; q < 2; q++) {
            int slot = tid * 2 + q;                        // 512 float4 slots
            int m = slot >> 2, kq = slot & 3;
            float4 v = *(const float4*)(asrc + (row0 + m) * 128 + kc + kq * 4);
            As[buf][kq * 4 + 0][m] = v.x;
            As[buf][kq * 4 + 1][m] = v.y;
            As[buf][kq * 4 + 2][m] = v.z;
            As[buf][kq * 4 + 3][m] = v.w;
        }
#pragma unroll
        for (int q = 0; q < 2; q++) {
            int slot = tid * 2 + q;
            int kr = slot >> 5, c4 = slot & 31;
            *(float4*)&Bs[buf][kr][c4 * 4] =
                *(const float4*)(wsrc + (size_t)(kc + kr) * 128 + c4 * 4);
        }
    };

    loadStage(0, 0);
    __syncthreads();
    int buf = 0;
#pragma unroll 1
    for (int s = 0; s < 16; s++) {
        if (s < 15) loadStage(s + 1, buf ^ 1);
#pragma unroll
        for (int k = 0; k < 16; k++) {
            unsigned long long a2[4], b2[8];
#pragma unroll
            for (int i = 0; i < 4; i++)
                a2[i] = *(const unsigned long long*)&As[buf][k][ty * 8 + i * 2];
#pragma unroll
            for (int j = 0; j < 8; j++) {
                unsigned int bb = __float_as_uint(Bs[buf][k][tx * 8 + j]);
                asm("mov.b64 %0, {%1,%1};" : "=l"(b2[j]) : "r"(bb));
            }
#pragma unroll
            for (int i = 0; i < 4; i++)
#pragma unroll
                for (int j = 0; j < 8; j++)
                    asm("fma.rn.f32x2 %0, %1, %2, %0;"
                        : "+l"(accp[i][j]) : "l"(a2[i]), "l"(b2[j]));
        }
        __syncthreads();
        buf ^= 1;
    }

    float bcol[8];
#pragma unroll
    for (int j = 0; j < 8; j++) bcol[j] = bias[tx * 8 + j];
#pragma unroll
    for (int i = 0; i < 4; i++) {
        float lo[8], hi[8];
#pragma unroll
        for (int j = 0; j < 8; j++) {
            unsigned long long v = accp[i][j];
            lo[j] = __uint_as_float((unsigned int)v);
            hi[j] = __uint_as_float((unsigned int)(v >> 32));
        }
        size_t r = row0 + ty * 8 + i * 2;
        float4 o;
        o.x = fmaxf(lo[0] + bcol[0], 0.f); o.y = fmaxf(lo[1] + bcol[1], 0.f);
        o.z = fmaxf(lo[2] + bcol[2], 0.f); o.w = fmaxf(lo[3] + bcol[3], 0.f);
        *(float4*)(g_x + r * 128 + tx * 8) = o;
        o.x = fmaxf(lo[4] + bcol[4], 0.f); o.y = fmaxf(lo[5] + bcol[5], 0.f);
        o.z = fmaxf(lo[6] + bcol[6], 0.f); o.w = fmaxf(lo[7] + bcol[7], 0.f);
        *(float4*)(g_x + r * 128 + tx * 8 + 4) = o;
        o.x = fmaxf(hi[0] + bcol[0], 0.f); o.y = fmaxf(hi[1] + bcol[1], 0.f);
        o.z = fmaxf(hi[2] + bcol[2], 0.f); o.w = fmaxf(hi[3] + bcol[3], 0.f);
        *(float4*)(g_x + (r + 1) * 128 + tx * 8) = o;
        o.x = fmaxf(hi[4] + bcol[4], 0.f); o.y = fmaxf(hi[5] + bcol[5], 0.f);
        o.z = fmaxf(hi[6] + bcol[6], 0.f); o.w = fmaxf(hi[7] + bcol[7], 0.f);
        *(float4*)(g_x + (r + 1) * 128 + tx * 8 + 4) = o;
    }
}

// ---------------- pooling + MLP head ----------------
__global__ void k_pool() {
    int c = blockIdx.y, tid = threadIdx.x;
    int n0 = blockIdx.x * 250;
    const float* xb = g_x + ((size_t)c * N_ + n0) * D_ + tid;
    float acc = 0.f;
#pragma unroll 5
    for (int i = 0; i < 250; i++) acc += xb[(size_t)i * D_];
    atomicAdd(&g_pool[c * D_ + tid], acc);
}

__global__ void k_mlp(const float* __restrict__ Wd1, const float* __restrict__ bd1,
                      const float* __restrict__ Wd2, const float* __restrict__ bd2,
                      const float* __restrict__ Wd3, const float* __restrict__ bd3,
                      float* __restrict__ out) {
    __shared__ float sa[C_][D_];
    __shared__ float sb[C_][D_];
    int tid = threadIdx.x;
    for (int i = tid; i < C_ * D_; i += D_) sa[i / D_][i % D_] = g_pool[i] * (1.0f / N_);
    __syncthreads();
    for (int c = 0; c < C_; c++) {
        float a = bd1[tid];
#pragma unroll 8
        for (int k = 0; k < D_; k++) a += sa[c][k] * Wd1[k * D_ + tid];
        sb[c][tid] = fmaxf(a, 0.f);
    }
    __syncthreads();
    for (int c = 0; c < C_; c++) {
        float a = bd2[tid];
#pragma unroll 8
        for (int k = 0; k < D_; k++) a += sb[c][k] * Wd2[k * D_ + tid];
        sa[c][tid] = fmaxf(a, 0.f);
    }
    __syncthreads();
    if (tid < C_) {
        float a = bd3[0];
#pragma unroll 8
        for (int k = 0; k < D_; k++) a += sa[tid][k] * Wd3[k];
        out[tid] = a;
    }
}

// ---------------- launch ----------------
extern "C" void kernel_launch(void* const* d_in, const int* in_sizes, int n_in,
                              void* d_out, int out_size) {
    (void)n_in; (void)out_size;
    const float* x_node_cfg      = (const float*)d_in[0];
    const float* x_feat          = (const float*)d_in[1];
    const int*   x_op            = (const int*)d_in[2];
    const int*   edge_index      = (const int*)d_in[3];
    const int*   node_config_ids = (const int*)d_in[4];
    const float* emb_table       = (const float*)d_in[5];
    const float* W_lin           = (const float*)d_in[6];
    const float* b_lin           = (const float*)d_in[7];
    const float* conv_Wl         = (const float*)d_in[8];
    const float* conv_Wr         = (const float*)d_in[9];
    const float* conv_b          = (const float*)d_in[10];
    const float* Wd1             = (const float*)d_in[11];
    const float* bd1             = (const float*)d_in[12];
    const float* Wd2             = (const float*)d_in[13];
    const float* bd2             = (const float*)d_in[14];
    const float* Wd3             = (const float*)d_in[15];
    const float* bd3             = (const float*)d_in[16];
    float* out = (float*)d_out;

    int E = in_sizes[3] / 2;
    const int* e_src = edge_index;
    const int* e_dst = edge_index + E;

    void *p_cnt, *p_fill, *p_pool;
    cudaGetSymbolAddress(&p_cnt,  g_cnt);
    cudaGetSymbolAddress(&p_fill, g_fill);
    cudaGetSymbolAddress(&p_pool, g_pool);
    cudaMemsetAsync(p_cnt,  0, N_ * sizeof(int));
    cudaMemsetAsync(p_fill, 0, N_ * sizeof(int));
    cudaMemsetAsync(p_pool, 0, C_ * D_ * sizeof(float));

    k_count<<<(E + 255) / 256, 256>>>(e_dst, E);
    k_scan<<<1, 1024>>>();
    k_fill<<<(E + 255) / 256, 256>>>(e_src, e_dst, E);

    k_bias2<<<1, 128>>>(W_lin, b_lin);
    k_base<<<N_ / 16, 128>>>(x_feat, x_op, emb_table, W_lin);

    dim3 gb(N_ * (D_ / 4) / 256, C_);
    k_broadcast<<<gb, 256>>>();
    dim3 gc(NC_, C_);
    k_correct<<<gc, 128>>>(x_node_cfg, node_config_ids, W_lin);

    for (int l = 0; l < L_; l++) {
        k_prop<<<(C_ * N_) / 8, 256>>>();
        k_gemm<<<(C_ * N_) / 128, 256>>>(conv_Wl + (size_t)l * D_ * D_,
                                         conv_Wr + (size_t)l * D_ * D_,
                                         conv_b + (size_t)l * D_);
    }

    dim3 gp(N_ / 250, C_);
    k_pool<<<gp, 128>>>();
    k_mlp<<<1, 128>>>(Wd1, bd1, Wd2, bd2, Wd3, bd3, out);
}

// round 3
// speedup vs baseline: 1.7930x; 1.7930x over previous
#include <cuda_runtime.h>
#include <cuda_fp16.h>
#include <math.h>
#include <stdint.h>

#define C_     32
#define NC_    2000
#define N_     10000
#define E_     30000
#define D_     128
#define L_     4
#define F_FEAT 140
#define F_CFG  18
#define F_EMB  4
#define TILES_ ((C_ * N_) / 128)       // 2500
#define GEMM_CTAS 152

// ---------------- scratch (static device globals; no allocation) ----------------
__device__ float g_x   [(size_t)C_ * N_ * D_];   // activations  (C,N,128)
__device__ float g_agg [(size_t)C_ * N_ * D_];   // propagated   (C,N,128)
__device__ float g_base[(size_t)N_ * D_];        // config-independent input projection
__device__ float g_invdeg[N_];
__device__ int   g_cnt [N_];
__device__ int   g_fill[N_];
__device__ int   g_indptr[N_ + 1];
__device__ int   g_csr[E_];
__device__ float g_pool[C_ * D_];
__device__ float g_Wt  [(size_t)L_ * 128 * 256]; // transposed combined weights [l][n][k]

// ================= mma.sync helpers (sm_80+ PTX; compiles under compute_103) =====
__device__ __forceinline__ uint32_t smem_u32(const void* p) {
    uint32_t a;
    asm("{ .reg .u64 t; cvta.to.shared.u64 t, %1; cvt.u32.u64 %0, t; }" : "=r"(a) : "l"(p));
    return a;
}
__device__ __forceinline__ void ldsm_x4(uint32_t* r, uint32_t addr) {
    asm volatile("ldmatrix.sync.aligned.m8n8.x4.shared.b16 {%0,%1,%2,%3}, [%4];"
                 : "=r"(r[0]), "=r"(r[1]), "=r"(r[2]), "=r"(r[3]) : "r"(addr));
}
__device__ __forceinline__ void ldsm_x2(uint32_t* r, uint32_t addr) {
    asm volatile("ldmatrix.sync.aligned.m8n8.x2.shared.b16 {%0,%1}, [%2];"
                 : "=r"(r[0]), "=r"(r[1]) : "r"(addr));
}
__device__ __forceinline__ void mma16816(float* c, const uint32_t* a, const uint32_t* b) {
    asm volatile("mma.sync.aligned.m16n8k16.row.col.f32.f16.f16.f32 "
                 "{%0,%1,%2,%3}, {%4,%5,%6,%7}, {%8,%9}, {%0,%1,%2,%3};"
                 : "+f"(c[0]), "+f"(c[1]), "+f"(c[2]), "+f"(c[3])
                 : "r"(a[0]), "r"(a[1]), "r"(a[2]), "r"(a[3]), "r"(b[0]), "r"(b[1]));
}

// ---------------- graph preprocessing ----------------
__global__ void k_count(const int* __restrict__ dst, int E) {
    int e = blockIdx.x * blockDim.x + threadIdx.x;
    if (e < E) atomicAdd(&g_cnt[dst[e]], 1);
}

__global__ void k_scan() {
    const int T = 1024, CH = 10;
    int t = threadIdx.x;
    int base = t * CH;
    int vals[CH];
    int s = 0;
#pragma unroll
    for (int i = 0; i < CH; i++) {
        int idx = base + i;
        int v = (idx < N_) ? g_cnt[idx] : 0;
        vals[i] = v; s += v;
    }
    int lane = t & 31, wid = t >> 5;
    int inc = s;
#pragma unroll
    for (int o = 1; o < 32; o <<= 1) {
        int y = __shfl_up_sync(0xffffffffu, inc, o);
        if (lane >= o) inc += y;
    }
    __shared__ int wtot[32];
    if (lane == 31) wtot[wid] = inc;
    __syncthreads();
    if (wid == 0) {
        int v = wtot[lane];
#pragma unroll
        for (int o = 1; o < 32; o <<= 1) {
            int y = __shfl_up_sync(0xffffffffu, v, o);
            if (lane >= o) v += y;
        }
        wtot[lane] = v;
    }
    __syncthreads();
    int excl = inc - s + (wid > 0 ? wtot[wid - 1] : 0);
    int run = excl;
#pragma unroll
    for (int i = 0; i < CH; i++) {
        int idx = base + i;
        if (idx < N_) {
            g_indptr[idx] = run;
            g_invdeg[idx] = 1.0f / fmaxf((float)vals[i], 1.0f);
        }
        run += vals[i];
    }
    if (t == T - 1) g_indptr[N_] = run;
}

__global__ void k_fill(const int* __restrict__ src, const int* __restrict__ dst, int E) {
    int e = blockIdx.x * blockDim.x + threadIdx.x;
    if (e < E) {
        int d = dst[e];
        int pos = g_indptr[d] + atomicAdd(&g_fill[d], 1);
        g_csr[pos] = src[e];
    }
}

// ---------------- weight transpose: g_Wt[l][n][k] ----------------
__global__ void k_wt(const float* __restrict__ Wl, const float* __restrict__ Wr) {
    int idx = blockIdx.x * 256 + threadIdx.x;       // 4*128*256 = 131072
    int l = idx >> 15;
    int rem = idx & 32767;
    int n = rem >> 8, k = rem & 255;
    float v = (k < 128) ? Wl[((size_t)l * 128 + k) * 128 + n]
                        : Wr[((size_t)l * 128 + (k - 128)) * 128 + n];
    g_Wt[idx] = v;
}

// ---------------- input projection ----------------
__global__ void k_base(const float* __restrict__ x_feat, const int* __restrict__ x_op,
                       const float* __restrict__ emb, const float* __restrict__ W_lin,
                       const float* __restrict__ b_lin) {
    __shared__ float s_in[16][F_FEAT + F_EMB];
    int n0 = blockIdx.x * 16;
    int tid = threadIdx.x;
    for (int i = tid; i < 16 * F_FEAT; i += 128) {
        int m = i / F_FEAT, k = i % F_FEAT;
        s_in[m][k] = x_feat[(size_t)(n0 + m) * F_FEAT + k];
    }
    if (tid < 16 * F_EMB) {
        int m = tid / F_EMB, k = tid % F_EMB;
        s_in[m][F_FEAT + k] = emb[x_op[n0 + m] * F_EMB + k];
    }
    __syncthreads();
    // bias2 = b_lin - 2*sum W_cfg rows
    float b = b_lin[tid];
#pragma unroll
    for (int k = 0; k < F_CFG; k++) b -= 2.0f * W_lin[(F_FEAT + k) * D_ + tid];
    float acc[16];
#pragma unroll
    for (int m = 0; m < 16; m++) acc[m] = b;
    const float* Wc = W_lin + tid;
#pragma unroll 4
    for (int k = 0; k < F_FEAT; k++) {
        float w = Wc[k * D_];
#pragma unroll
        for (int m = 0; m < 16; m++) acc[m] += s_in[m][k] * w;
    }
#pragma unroll
    for (int k = 0; k < F_EMB; k++) {
        float w = Wc[(F_FEAT + F_CFG + k) * D_];
#pragma unroll
        for (int m = 0; m < 16; m++) acc[m] += s_in[m][F_FEAT + k] * w;
    }
#pragma unroll
    for (int m = 0; m < 16; m++) g_base[(size_t)(n0 + m) * D_ + tid] = acc[m];
}

__global__ void k_broadcast() {
    int c = blockIdx.y;
    int i = blockIdx.x * blockDim.x + threadIdx.x;
    float4 v = ((const float4*)g_base)[i];
    ((float4*)g_x)[(size_t)c * (N_ * (D_ / 4)) + i] = v;
}

__global__ void k_correct(const float* __restrict__ xcfg, const int* __restrict__ nid,
                          const float* __restrict__ W_lin) {
    int j = blockIdx.x, c = blockIdx.y, tid = threadIdx.x;
    int n = nid[j];
    if (j < NC_ - 1 && nid[j + 1] == n) return;
    __shared__ float s_cfg[F_CFG];
    if (tid < F_CFG) s_cfg[tid] = xcfg[((size_t)c * NC_ + j) * F_CFG + tid] + 2.0f;
    __syncthreads();
    float acc = 0.f;
#pragma unroll
    for (int k = 0; k < F_CFG; k++) acc += s_cfg[k] * W_lin[(F_FEAT + k) * D_ + tid];
    g_x[((size_t)c * N_ + n) * D_ + tid] += acc;
}

// ---------------- GNN propagation ----------------
__global__ void k_prop() {
    int gw = (blockIdx.x * blockDim.x + threadIdx.x) >> 5;
    int lane = threadIdx.x & 31;
    if (gw >= C_ * N_) return;
    int c = gw / N_, n = gw - c * N_;
    int beg = g_indptr[n], end = g_indptr[n + 1];
    const float* xb = g_x + (size_t)c * N_ * D_;
    float4 s = make_float4(0.f, 0.f, 0.f, 0.f);
    for (int e = beg; e < end; e++) {
        int src = g_csr[e];
        float4 v = *(const float4*)(xb + (size_t)src * D_ + lane * 4);
        s.x += v.x; s.y += v.y; s.z += v.z; s.w += v.w;
    }
    float id = g_invdeg[n];
    s.x *= id; s.y *= id; s.z *= id; s.w *= id;
    *(float4*)(g_agg + ((size_t)c * N_ + n) * D_ + lane * 4) = s;
}

// ---------------- mma.sync fp16-split dual GEMM ----------------
// x = relu([agg|x] @ Wt^T + b). 128x128 tile, K=256 in 4 chunks of 64.
// fp16 two-term split, 3 cross products, fp32 accumulate.
// SMEM: B hi/lo per chunk persistent (147456 B), A hi/lo double-buffered (73728 B).
#define ASTRIDE_B 144               // bytes per row (72 halfs): 128+16 -> conflict-free ldmatrix
#define PLANE_B   18432             // 128 rows * 144 B
#define B_BYTES   (4 * 2 * PLANE_B) // 147456
#define A_BYTES   (2 * 2 * PLANE_B) // 73728
#define SMEM_GEMM (B_BYTES + A_BYTES)

__global__ void __launch_bounds__(256, 1) k_gemm_mma(int layer, const float* __restrict__ conv_b) {
    extern __shared__ __align__(16) char sm[];
    char* Bsm = sm;
    char* Asm = sm + B_BYTES;
    __shared__ float s_bias[128];

    const int tid = threadIdx.x;
    const int lane = tid & 31;
    const int wid = tid >> 5;
    const int wm = wid >> 2;            // 0..1  (64 rows each)
    const int wn = wid & 3;             // 0..3  (32 cols each)
    const int m0 = wm * 64, n0 = wn * 32;

    if (tid < 128) s_bias[tid] = conv_b[(size_t)layer * D_ + tid];

    // ---- load + split weights into SMEM: Bs[chunk][plane][n][72] ----
    {
        const float* W = g_Wt + (size_t)layer * 32768;
#pragma unroll
        for (int i = 0; i < 32; i++) {
            int f = i * 256 + tid;              // 8192 float4 over [n=128][k=256]
            int n = f >> 6, q = f & 63;         // kglob = q*4
            float4 v = *(const float4*)(W + (size_t)n * 256 + q * 4);
            int chunk = q >> 4;
            int kq = q & 15;                    // k' = kq*4 within chunk
            __half2 h01 = __floats2half2_rn(v.x, v.y);
            __half2 h23 = __floats2half2_rn(v.z, v.w);
            float2 f01 = __half22float2(h01), f23 = __half22float2(h23);
            __half2 l01 = __floats2half2_rn(v.x - f01.x, v.y - f01.y);
            __half2 l23 = __floats2half2_rn(v.z - f23.x, v.w - f23.y);
            char* dh = Bsm + chunk * 2 * PLANE_B + n * ASTRIDE_B + kq * 8;
            uint2 uh; uh.x = *(uint32_t*)&h01; uh.y = *(uint32_t*)&h23;
            uint2 ul; ul.x = *(uint32_t*)&l01; ul.y = *(uint32_t*)&l23;
            *(uint2*)dh = uh;
            *(uint2*)(dh + PLANE_B) = ul;
        }
    }
    __syncthreads();

    const uint32_t a_u32 = smem_u32(Asm);
    const uint32_t b_u32 = smem_u32(Bsm);

    for (int t = blockIdx.x; t < TILES_; t += gridDim.x) {
        const size_t row0 = (size_t)t * 128;

        float acc[4][4][4];
#pragma unroll
        for (int mi = 0; mi < 4; mi++)
#pragma unroll
            for (int ni = 0; ni < 4; ni++)
#pragma unroll
                for (int q = 0; q < 4; q++) acc[mi][ni][q] = 0.f;

        float4 av[8];
        // prologue: chunk 0
        {
            const float* src = g_agg + row0 * 128;
#pragma unroll
            for (int i = 0; i < 8; i++) {
                int f = i * 256 + tid, r = f >> 4, q = f & 15;
                av[i] = *(const float4*)(src + (size_t)r * 128 + q * 4);
            }
#pragma unroll
            for (int i = 0; i < 8; i++) {
                int f = i * 256 + tid, r = f >> 4, q = f & 15;
                __half2 h01 = __floats2half2_rn(av[i].x, av[i].y);
                __half2 h23 = __floats2half2_rn(av[i].z, av[i].w);
                float2 f01 = __half22float2(h01), f23 = __half22float2(h23);
                __half2 l01 = __floats2half2_rn(av[i].x - f01.x, av[i].y - f01.y);
                __half2 l23 = __floats2half2_rn(av[i].z - f23.x, av[i].w - f23.y);
                char* dh = Asm + r * ASTRIDE_B + q * 8;
                uint2 uh; uh.x = *(uint32_t*)&h01; uh.y = *(uint32_t*)&h23;
                uint2 ul; ul.x = *(uint32_t*)&l01; ul.y = *(uint32_t*)&l23;
                *(uint2*)dh = uh;
                *(uint2*)(dh + PLANE_B) = ul;
            }
        }
        __syncthreads();

#pragma unroll 1
        for (int s = 0; s < 4; s++) {
            // prefetch chunk s+1 into registers (overlaps the MMA work below)
            if (s < 3) {
                const float* src = ((s + 1 < 2) ? g_agg : g_x) + row0 * 128 + ((s + 1) & 1) * 64;
#pragma unroll
                for (int i = 0; i < 8; i++) {
                    int f = i * 256 + tid, r = f >> 4, q = f & 15;
                    av[i] = *(const float4*)(src + (size_t)r * 128 + q * 4);
                }
            }

            // compute chunk s from buffer (s&1)
            const uint32_t abase = a_u32 + (s & 1) * (2 * PLANE_B);
            const uint32_t bbase = b_u32 + s * (2 * PLANE_B);
#pragma unroll
            for (int ks = 0; ks < 4; ks++) {
                const int kofs = ks * 16;
                uint32_t ah[4][4], al[4][4], bh[4][2], bl[4][2];
#pragma unroll
                for (int mi = 0; mi < 4; mi++) {
                    uint32_t addr = abase + (uint32_t)(m0 + mi * 16 + (lane & 15)) * ASTRIDE_B
                                  + (uint32_t)(kofs + (lane >> 4) * 8) * 2;
                    ldsm_x4(ah[mi], addr);
                    ldsm_x4(al[mi], addr + PLANE_B);
                }
#pragma unroll
                for (int ni = 0; ni < 4; ni++) {
                    uint32_t addr = bbase + (uint32_t)(n0 + ni * 8 + (lane & 7)) * ASTRIDE_B
                                  + (uint32_t)(kofs + ((lane >> 3) & 1) * 8) * 2;
                    ldsm_x2(bh[ni], addr);
                    ldsm_x2(bl[ni], addr + PLANE_B);
                }
#pragma unroll
                for (int mi = 0; mi < 4; mi++)
#pragma unroll
                    for (int ni = 0; ni < 4; ni++) {
                        mma16816(acc[mi][ni], ah[mi], bh[ni]);
                        mma16816(acc[mi][ni], ah[mi], bl[ni]);
                        mma16816(acc[mi][ni], al[mi], bh[ni]);
                    }
            }

            if (s < 3) {
                __syncthreads();                 // all warps done reading buffer (s+1)&1
                const int b = (s + 1) & 1;
#pragma unroll
                for (int i = 0; i < 8; i++) {
                    int f = i * 256 + tid, r = f >> 4, q = f & 15;
                    __half2 h01 = __floats2half2_rn(av[i].x, av[i].y);
                    __half2 h23 = __floats2half2_rn(av[i].z, av[i].w);
                    float2 f01 = __half22float2(h01), f23 = __half22float2(h23);
                    __half2 l01 = __floats2half2_rn(av[i].x - f01.x, av[i].y - f01.y);
                    __half2 l23 = __floats2half2_rn(av[i].z - f23.x, av[i].w - f23.y);
                    char* dh = Asm + b * (2 * PLANE_B) + r * ASTRIDE_B + q * 8;
                    uint2 uh; uh.x = *(uint32_t*)&h01; uh.y = *(uint32_t*)&h23;
                    uint2 ul; ul.x = *(uint32_t*)&l01; ul.y = *(uint32_t*)&l23;
                    *(uint2*)dh = uh;
                    *(uint2*)(dh + PLANE_B) = ul;
                }
                __syncthreads();
            }
        }

        // ---- epilogue: bias + relu, direct fp32 store ----
#pragma unroll
        for (int mi = 0; mi < 4; mi++) {
            size_t r0 = row0 + m0 + mi * 16 + (lane >> 2);
            size_t r1 = r0 + 8;
#pragma unroll
            for (int ni = 0; ni < 4; ni++) {
                int col = n0 + ni * 8 + (lane & 3) * 2;
                float b0 = s_bias[col], b1 = s_bias[col + 1];
                float2 o0, o1;
                o0.x = fmaxf(acc[mi][ni][0] + b0, 0.f);
                o0.y = fmaxf(acc[mi][ni][1] + b1, 0.f);
                o1.x = fmaxf(acc[mi][ni][2] + b0, 0.f);
                o1.y = fmaxf(acc[mi][ni][3] + b1, 0.f);
                *(float2*)(g_x + r0 * 128 + col) = o0;
                *(float2*)(g_x + r1 * 128 + col) = o1;
            }
        }
        __syncthreads();   // A buffers reused next tile
    }
}

// ---------------- pooling + MLP head ----------------
__global__ void k_pool() {
    int c = blockIdx.y, tid = threadIdx.x;
    int n0 = blockIdx.x * 250;
    const float* xb = g_x + ((size_t)c * N_ + n0) * D_ + tid;
    float acc = 0.f;
#pragma unroll 5
    for (int i = 0; i < 250; i++) acc += xb[(size_t)i * D_];
    atomicAdd(&g_pool[c * D_ + tid], acc);
}

__global__ void k_mlp(const float* __restrict__ Wd1, const float* __restrict__ bd1,
                      const float* __restrict__ Wd2, const float* __restrict__ bd2,
                      const float* __restrict__ Wd3, const float* __restrict__ bd3,
                      float* __restrict__ out) {
    __shared__ float sa[C_][D_];
    __shared__ float sb[C_][D_];
    int tid = threadIdx.x;
    for (int i = tid; i < C_ * D_; i += D_) sa[i / D_][i % D_] = g_pool[i] * (1.0f / N_);
    __syncthreads();
    for (int c = 0; c < C_; c++) {
        float a = bd1[tid];
#pragma unroll 8
        for (int k = 0; k < D_; k++) a += sa[c][k] * Wd1[k * D_ + tid];
        sb[c][tid] = fmaxf(a, 0.f);
    }
    __syncthreads();
    for (int c = 0; c < C_; c++) {
        float a = bd2[tid];
#pragma unroll 8
        for (int k = 0; k < D_; k++) a += sb[c][k] * Wd2[k * D_ + tid];
        sa[c][tid] = fmaxf(a, 0.f);
    }
    __syncthreads();
    if (tid < C_) {
        float a = bd3[0];
#pragma unroll 8
        for (int k = 0; k < D_; k++) a += sa[tid][k] * Wd3[k];
        out[tid] = a;
    }
}

// ---------------- launch ----------------
extern "C" void kernel_launch(void* const* d_in, const int* in_sizes, int n_in,
                              void* d_out, int out_size) {
    (void)n_in; (void)out_size;
    const float* x_node_cfg      = (const float*)d_in[0];
    const float* x_feat          = (const float*)d_in[1];
    const int*   x_op            = (const int*)d_in[2];
    const int*   edge_index      = (const int*)d_in[3];
    const int*   node_config_ids = (const int*)d_in[4];
    const float* emb_table       = (const float*)d_in[5];
    const float* W_lin           = (const float*)d_in[6];
    const float* b_lin           = (const float*)d_in[7];
    const float* conv_Wl         = (const float*)d_in[8];
    const float* conv_Wr         = (const float*)d_in[9];
    const float* conv_b          = (const float*)d_in[10];
    const float* Wd1             = (const float*)d_in[11];
    const float* bd1             = (const float*)d_in[12];
    const float* Wd2             = (const float*)d_in[13];
    const float* bd2             = (const float*)d_in[14];
    const float* Wd3             = (const float*)d_in[15];
    const float* bd3             = (const float*)d_in[16];
    float* out = (float*)d_out;

    int E = in_sizes[3] / 2;
    const int* e_src = edge_index;
    const int* e_dst = edge_index + E;

    static int smem_set = 0;
    if (!smem_set) {
        cudaFuncSetAttribute(k_gemm_mma, cudaFuncAttributeMaxDynamicSharedMemorySize, SMEM_GEMM);
        smem_set = 1;
    }

    void *p_cnt, *p_fill, *p_pool;
    cudaGetSymbolAddress(&p_cnt,  g_cnt);
    cudaGetSymbolAddress(&p_fill, g_fill);
    cudaGetSymbolAddress(&p_pool, g_pool);
    cudaMemsetAsync(p_cnt,  0, N_ * sizeof(int));
    cudaMemsetAsync(p_fill, 0, N_ * sizeof(int));
    cudaMemsetAsync(p_pool, 0, C_ * D_ * sizeof(float));

    k_count<<<(E + 255) / 256, 256>>>(e_dst, E);
    k_scan<<<1, 1024>>>();
    k_fill<<<(E + 255) / 256, 256>>>(e_src, e_dst, E);

    k_wt<<<512, 256>>>(conv_Wl, conv_Wr);
    k_base<<<N_ / 16, 128>>>(x_feat, x_op, emb_table, W_lin, b_lin);

    dim3 gb(N_ * (D_ / 4) / 256, C_);
    k_broadcast<<<gb, 256>>>();
    dim3 gc(NC_, C_);
    k_correct<<<gc, 128>>>(x_node_cfg, node_config_ids, W_lin);

    for (int l = 0; l < L_; l++) {
        k_prop<<<(C_ * N_) / 8, 256>>>();
        k_gemm_mma<<<GEMM_CTAS, 256, SMEM_GEMM>>>(l, conv_b);
    }

    dim3 gp(N_ / 250, C_);
    k_pool<<<gp, 128>>>();
    k_mlp<<<1, 128>>>(Wd1, bd1, Wd2, bd2, Wd3, bd3, out);
}